// round 1
// baseline (speedup 1.0000x reference)
#include <cuda_runtime.h>

#define Bb 64
#define Cc 256
#define Hh 64
#define Ww 64
#define Ss (Hh*Ww)   // 4096
#define HID 16

// scratch (no allocations allowed)
__device__ float g_z[Bb*Ss];      // channel-contracted logits pre-pool
__device__ float g_attn[Bb*Ss];   // softmax attention
__device__ float g_y[Bb*Cc];      // attention-pooled features
__device__ float g_gate[Bb*Cc];   // SE gate

// ---------------------------------------------------------------------------
// K1: z[b][s] = sum_c x[b][c][s] * conv_w[c]
// grid = Bb * (Ss/1024) = 256 blocks, 256 threads, float4 per thread
// ---------------------------------------------------------------------------
__global__ void k1_channel_dot(const float* __restrict__ x,
                               const float* __restrict__ conv_w) {
    __shared__ float wsh[Cc];
    wsh[threadIdx.x] = conv_w[threadIdx.x];
    __syncthreads();

    int blk = blockIdx.x;
    int b = blk >> 2;                                // Ss/1024 = 4 blocks per batch
    int s4 = ((blk & 3) << 8) + threadIdx.x;         // float4 index in [0,1024)
    const float4* x4 = reinterpret_cast<const float4*>(x + (size_t)b * Cc * Ss) + s4;

    float4 acc = make_float4(0.f, 0.f, 0.f, 0.f);
#pragma unroll 8
    for (int c = 0; c < Cc; c++) {
        float w = wsh[c];
        float4 v = x4[(size_t)c * (Ss / 4)];
        acc.x = fmaf(v.x, w, acc.x);
        acc.y = fmaf(v.y, w, acc.y);
        acc.z = fmaf(v.z, w, acc.z);
        acc.w = fmaf(v.w, w, acc.w);
    }
    reinterpret_cast<float4*>(g_z + (size_t)b * Ss)[s4] = acc;
}

// ---------------------------------------------------------------------------
// K2: 3x3x3 avg pool (t within group-of-8, h, w; zero pad; /27) + bias + softmax
// one block per batch (64 blocks, 256 threads)
// ---------------------------------------------------------------------------
__global__ void k2_pool_softmax(const float* __restrict__ conv_b) {
    __shared__ float zs[Ss];     // t-summed slice (16 KB)
    __shared__ float red[32];

    int b = blockIdx.x;
    int g = b >> 3;
    int t = b & 7;
    int tlo = (t > 0) ? t - 1 : 0;
    int thi = (t < 7) ? t + 1 : 7;

    for (int i = threadIdx.x; i < Ss; i += blockDim.x) {
        float v = 0.f;
        for (int tt = tlo; tt <= thi; tt++)
            v += g_z[(g * 8 + tt) * Ss + i];
        zs[i] = v;
    }
    __syncthreads();

    const float cb = conv_b[0];
    float lg[16];
    float lmax = -1e30f;
#pragma unroll
    for (int i = 0; i < 16; i++) {
        int s = threadIdx.x + (i << 8);
        int h = s >> 6, w = s & 63;
        float sum = 0.f;
#pragma unroll
        for (int dh = -1; dh <= 1; dh++) {
            int hh = h + dh;
            if (hh < 0 || hh >= Hh) continue;
#pragma unroll
            for (int dw = -1; dw <= 1; dw++) {
                int ww = w + dw;
                if (ww < 0 || ww >= Ww) continue;
                sum += zs[(hh << 6) + ww];
            }
        }
        float l = sum * (1.f / 27.f) + cb;
        lg[i] = l;
        lmax = fmaxf(lmax, l);
    }

    // block max
    for (int o = 16; o; o >>= 1) lmax = fmaxf(lmax, __shfl_xor_sync(0xffffffffu, lmax, o));
    if ((threadIdx.x & 31) == 0) red[threadIdx.x >> 5] = lmax;
    __syncthreads();
    if (threadIdx.x < 32) {
        float v = (threadIdx.x < 8) ? red[threadIdx.x] : -1e30f;
        for (int o = 4; o; o >>= 1) v = fmaxf(v, __shfl_xor_sync(0xffffffffu, v, o));
        if (threadIdx.x == 0) red[0] = v;
    }
    __syncthreads();
    lmax = red[0];
    __syncthreads();   // protect red[] before reuse

    float lsum = 0.f;
#pragma unroll
    for (int i = 0; i < 16; i++) {
        lg[i] = expf(lg[i] - lmax);
        lsum += lg[i];
    }
    for (int o = 16; o; o >>= 1) lsum += __shfl_xor_sync(0xffffffffu, lsum, o);
    if ((threadIdx.x & 31) == 0) red[threadIdx.x >> 5] = lsum;
    __syncthreads();
    if (threadIdx.x < 32) {
        float v = (threadIdx.x < 8) ? red[threadIdx.x] : 0.f;
        for (int o = 4; o; o >>= 1) v += __shfl_xor_sync(0xffffffffu, v, o);
        if (threadIdx.x == 0) red[0] = v;
    }
    __syncthreads();
    float inv = 1.f / red[0];
#pragma unroll
    for (int i = 0; i < 16; i++) {
        int s = threadIdx.x + (i << 8);
        g_attn[b * Ss + s] = lg[i] * inv;
    }
}

// ---------------------------------------------------------------------------
// K3: y[b][c] = sum_s x[b][c][s] * attn[b][s]
// grid = Bb*Cc = 16384 blocks, 128 threads
// ---------------------------------------------------------------------------
__global__ void k3_weighted_pool(const float* __restrict__ x) {
    int bc = blockIdx.x;
    int b = bc >> 8;      // Cc = 256
    const float4* x4 = reinterpret_cast<const float4*>(x + (size_t)bc * Ss);
    const float4* a4 = reinterpret_cast<const float4*>(g_attn + (size_t)b * Ss);

    float acc = 0.f;
#pragma unroll
    for (int i = threadIdx.x; i < Ss / 4; i += 128) {
        float4 v = x4[i];
        float4 a = a4[i];
        acc += v.x * a.x + v.y * a.y + v.z * a.z + v.w * a.w;
    }
    for (int o = 16; o; o >>= 1) acc += __shfl_xor_sync(0xffffffffu, acc, o);
    __shared__ float red[4];
    if ((threadIdx.x & 31) == 0) red[threadIdx.x >> 5] = acc;
    __syncthreads();
    if (threadIdx.x == 0)
        g_y[bc] = red[0] + red[1] + red[2] + red[3];
}

// ---------------------------------------------------------------------------
// K4: SE MLP: hid = relu(y @ fc1^T); gate = sigmoid(hid @ fc2^T)
// one block per batch, 256 threads
// ---------------------------------------------------------------------------
__global__ void k4_mlp(const float* __restrict__ fc1,
                       const float* __restrict__ fc2) {
    int b = blockIdx.x;
    __shared__ float ys[Cc];
    __shared__ float hs[HID];
    ys[threadIdx.x] = g_y[b * Cc + threadIdx.x];
    __syncthreads();
    if (threadIdx.x < HID) {
        float acc = 0.f;
        const float* w = fc1 + threadIdx.x * Cc;
#pragma unroll 8
        for (int c = 0; c < Cc; c++) acc = fmaf(ys[c], w[c], acc);
        hs[threadIdx.x] = fmaxf(acc, 0.f);
    }
    __syncthreads();
    float acc = 0.f;
    const float* w2 = fc2 + threadIdx.x * HID;
#pragma unroll
    for (int j = 0; j < HID; j++) acc = fmaf(hs[j], w2[j], acc);
    g_gate[b * Cc + threadIdx.x] = 1.f / (1.f + expf(-acc));
}

// ---------------------------------------------------------------------------
// K5: out = x * gate[b,c]   (float4, one per thread)
// grid = Bb*Cc*Ss/4/256 = 65536 blocks, 256 threads
// ---------------------------------------------------------------------------
__global__ void k5_scale(const float* __restrict__ x, float* __restrict__ out) {
    size_t i4 = (size_t)blockIdx.x * blockDim.x + threadIdx.x;
    float gv = g_gate[i4 >> 10];          // Ss/4 = 1024 float4 per (b,c)
    float4 v = reinterpret_cast<const float4*>(x)[i4];
    v.x *= gv; v.y *= gv; v.z *= gv; v.w *= gv;
    reinterpret_cast<float4*>(out)[i4] = v;
}

// ---------------------------------------------------------------------------
extern "C" void kernel_launch(void* const* d_in, const int* in_sizes, int n_in,
                              void* d_out, int out_size) {
    const float* x      = (const float*)d_in[0];
    const float* conv_w = (const float*)d_in[1];
    const float* conv_b = (const float*)d_in[2];
    const float* fc1_w  = (const float*)d_in[3];
    const float* fc2_w  = (const float*)d_in[4];
    float* out = (float*)d_out;

    k1_channel_dot<<<Bb * (Ss / 1024), 256>>>(x, conv_w);
    k2_pool_softmax<<<Bb, 256>>>(conv_b);
    k3_weighted_pool<<<Bb * Cc, 128>>>(x);
    k4_mlp<<<Bb, 256>>>(fc1_w, fc2_w);
    k5_scale<<<(size_t)Bb * Cc * Ss / 4 / 256, 256>>>(x, out);
}

// round 2
// speedup vs baseline: 1.1110x; 1.1110x over previous
#include <cuda_runtime.h>

#define Bb 64
#define Cc 256
#define Hh 64
#define Ww 64
#define Ss (Hh*Ww)   // 4096
#define HID 16

// scratch (no allocations allowed)
__device__ float g_z[Bb*Ss];      // channel-contracted logits pre-pool
__device__ float g_attn[Bb*Ss];   // softmax attention
__device__ float g_y[Bb*Cc];      // attention-pooled features
__device__ float g_gate[Bb*Cc];   // SE gate

// ---------------------------------------------------------------------------
// K1: z[b][s] = sum_c x[b][c][s] * conv_w[c]
// grid = Bb * 8 = 512 blocks, 128 threads, one float4 per thread
// ---------------------------------------------------------------------------
__global__ void k1_channel_dot(const float* __restrict__ x,
                               const float* __restrict__ conv_w) {
    __shared__ float wsh[Cc];
    if (threadIdx.x < Cc) {
        wsh[threadIdx.x] = conv_w[threadIdx.x];
        wsh[threadIdx.x + 128] = conv_w[threadIdx.x + 128];
    }
    __syncthreads();

    int blk = blockIdx.x;
    int b = blk >> 3;                                // 8 blocks per batch
    int s4 = ((blk & 7) << 7) + threadIdx.x;         // float4 index in [0,1024)
    const float4* x4 = reinterpret_cast<const float4*>(x + (size_t)b * Cc * Ss) + s4;

    float4 acc = make_float4(0.f, 0.f, 0.f, 0.f);
#pragma unroll 8
    for (int c = 0; c < Cc; c++) {
        float w = wsh[c];
        float4 v = x4[(size_t)c * (Ss / 4)];
        acc.x = fmaf(v.x, w, acc.x);
        acc.y = fmaf(v.y, w, acc.y);
        acc.z = fmaf(v.z, w, acc.z);
        acc.w = fmaf(v.w, w, acc.w);
    }
    reinterpret_cast<float4*>(g_z + (size_t)b * Ss)[s4] = acc;
}

// ---------------------------------------------------------------------------
// K2: 3x3x3 avg pool (t within group-of-8, h, w; zero pad; /27) + bias + softmax
// one block per batch (64 blocks, 256 threads)
// ---------------------------------------------------------------------------
__global__ void k2_pool_softmax(const float* __restrict__ conv_b) {
    __shared__ float zs[Ss];     // t-summed slice (16 KB)
    __shared__ float red[32];

    int b = blockIdx.x;
    int g = b >> 3;
    int t = b & 7;
    int tlo = (t > 0) ? t - 1 : 0;
    int thi = (t < 7) ? t + 1 : 7;

    // float4-vectorized t-sum: 1024 float4 over 256 threads
    {
        float4* zs4 = reinterpret_cast<float4*>(zs);
#pragma unroll
        for (int i = threadIdx.x; i < Ss / 4; i += 256) {
            float4 v = make_float4(0.f, 0.f, 0.f, 0.f);
            for (int tt = tlo; tt <= thi; tt++) {
                float4 u = reinterpret_cast<const float4*>(g_z + (g * 8 + tt) * Ss)[i];
                v.x += u.x; v.y += u.y; v.z += u.z; v.w += u.w;
            }
            zs4[i] = v;
        }
    }
    __syncthreads();

    const float cb = conv_b[0];
    float lg[16];
    float lmax = -1e30f;
#pragma unroll
    for (int i = 0; i < 16; i++) {
        int s = threadIdx.x + (i << 8);
        int h = s >> 6, w = s & 63;
        float sum = 0.f;
#pragma unroll
        for (int dh = -1; dh <= 1; dh++) {
            int hh = h + dh;
            if (hh < 0 || hh >= Hh) continue;
#pragma unroll
            for (int dw = -1; dw <= 1; dw++) {
                int ww = w + dw;
                if (ww < 0 || ww >= Ww) continue;
                sum += zs[(hh << 6) + ww];
            }
        }
        float l = sum * (1.f / 27.f) + cb;
        lg[i] = l;
        lmax = fmaxf(lmax, l);
    }

    // block max
    for (int o = 16; o; o >>= 1) lmax = fmaxf(lmax, __shfl_xor_sync(0xffffffffu, lmax, o));
    if ((threadIdx.x & 31) == 0) red[threadIdx.x >> 5] = lmax;
    __syncthreads();
    if (threadIdx.x < 32) {
        float v = (threadIdx.x < 8) ? red[threadIdx.x] : -1e30f;
        for (int o = 4; o; o >>= 1) v = fmaxf(v, __shfl_xor_sync(0xffffffffu, v, o));
        if (threadIdx.x == 0) red[0] = v;
    }
    __syncthreads();
    lmax = red[0];
    __syncthreads();   // protect red[] before reuse

    float lsum = 0.f;
#pragma unroll
    for (int i = 0; i < 16; i++) {
        lg[i] = expf(lg[i] - lmax);
        lsum += lg[i];
    }
    for (int o = 16; o; o >>= 1) lsum += __shfl_xor_sync(0xffffffffu, lsum, o);
    if ((threadIdx.x & 31) == 0) red[threadIdx.x >> 5] = lsum;
    __syncthreads();
    if (threadIdx.x < 32) {
        float v = (threadIdx.x < 8) ? red[threadIdx.x] : 0.f;
        for (int o = 4; o; o >>= 1) v += __shfl_xor_sync(0xffffffffu, v, o);
        if (threadIdx.x == 0) red[0] = v;
    }
    __syncthreads();
    float inv = 1.f / red[0];
#pragma unroll
    for (int i = 0; i < 16; i++) {
        int s = threadIdx.x + (i << 8);
        g_attn[b * Ss + s] = lg[i] * inv;
    }
}

// ---------------------------------------------------------------------------
// K3: y[b][c] = sum_s x[b][c][s] * attn[b][s]
// grid = Bb*Cc = 16384 blocks, 128 threads
// ---------------------------------------------------------------------------
__global__ void k3_weighted_pool(const float* __restrict__ x) {
    int bc = blockIdx.x;
    int b = bc >> 8;      // Cc = 256
    const float4* x4 = reinterpret_cast<const float4*>(x + (size_t)bc * Ss);
    const float4* a4 = reinterpret_cast<const float4*>(g_attn + (size_t)b * Ss);

    float acc = 0.f;
#pragma unroll
    for (int i = threadIdx.x; i < Ss / 4; i += 128) {
        float4 v = x4[i];
        float4 a = a4[i];
        acc += v.x * a.x + v.y * a.y + v.z * a.z + v.w * a.w;
    }
    for (int o = 16; o; o >>= 1) acc += __shfl_xor_sync(0xffffffffu, acc, o);
    __shared__ float red[4];
    if ((threadIdx.x & 31) == 0) red[threadIdx.x >> 5] = acc;
    __syncthreads();
    if (threadIdx.x == 0)
        g_y[bc] = red[0] + red[1] + red[2] + red[3];
}

// ---------------------------------------------------------------------------
// K4: SE MLP: hid = relu(y @ fc1^T); gate = sigmoid(hid @ fc2^T)
// one block per batch, 512 threads: warp w computes hid[w] (8 FMA + reduce),
// then threads 0..255 compute the gate (16 FMA each).
// ---------------------------------------------------------------------------
__global__ void k4_mlp(const float* __restrict__ fc1,
                       const float* __restrict__ fc2) {
    int b = blockIdx.x;
    int tid = threadIdx.x;
    __shared__ float ys[Cc];
    __shared__ float hs[HID];
    if (tid < Cc) ys[tid] = g_y[b * Cc + tid];
    __syncthreads();

    int warp = tid >> 5, lane = tid & 31;   // 16 warps == HID
    float acc = 0.f;
#pragma unroll
    for (int i = 0; i < Cc / 32; i++) {
        int c = lane + (i << 5);
        acc = fmaf(ys[c], fc1[warp * Cc + c], acc);
    }
    for (int o = 16; o; o >>= 1) acc += __shfl_xor_sync(0xffffffffu, acc, o);
    if (lane == 0) hs[warp] = fmaxf(acc, 0.f);
    __syncthreads();

    if (tid < Cc) {
        float a = 0.f;
        const float* w2 = fc2 + tid * HID;
#pragma unroll
        for (int j = 0; j < HID; j++) a = fmaf(hs[j], w2[j], a);
        g_gate[b * Cc + tid] = 1.f / (1.f + expf(-a));
    }
}

// ---------------------------------------------------------------------------
// K5: out = x * gate[b,c]   (float4, one per thread)
// grid = Bb*Cc*Ss/4/256 = 65536 blocks, 256 threads
// ---------------------------------------------------------------------------
__global__ void k5_scale(const float* __restrict__ x, float* __restrict__ out) {
    size_t i4 = (size_t)blockIdx.x * blockDim.x + threadIdx.x;
    float gv = g_gate[i4 >> 10];          // Ss/4 = 1024 float4 per (b,c)
    float4 v = reinterpret_cast<const float4*>(x)[i4];
    v.x *= gv; v.y *= gv; v.z *= gv; v.w *= gv;
    reinterpret_cast<float4*>(out)[i4] = v;
}

// ---------------------------------------------------------------------------
extern "C" void kernel_launch(void* const* d_in, const int* in_sizes, int n_in,
                              void* d_out, int out_size) {
    const float* x      = (const float*)d_in[0];
    const float* conv_w = (const float*)d_in[1];
    const float* conv_b = (const float*)d_in[2];
    const float* fc1_w  = (const float*)d_in[3];
    const float* fc2_w  = (const float*)d_in[4];
    float* out = (float*)d_out;

    k1_channel_dot<<<Bb * 8, 128>>>(x, conv_w);
    k2_pool_softmax<<<Bb, 256>>>(conv_b);
    k3_weighted_pool<<<Bb * Cc, 128>>>(x);
    k4_mlp<<<Bb, 512>>>(fc1_w, fc2_w);
    k5_scale<<<(size_t)Bb * Cc * Ss / 4 / 256, 256>>>(x, out);
}